// round 5
// baseline (speedup 1.0000x reference)
#include <cuda_runtime.h>

#define MAXN 100000
#define STR  132                  // node kernel padded stride (words)
#define TWORDS (128 * STR)
#define CSTR 132                  // edge C1 row stride (words)

static __device__ float g_msrc[(size_t)MAXN * 128];
static __device__ float g_mdst[(size_t)MAXN * 128];

// ---------------- common helpers ----------------
__device__ __forceinline__ unsigned smem_u32(const void* p) {
    unsigned a;
    asm("{ .reg .u64 t; cvta.to.shared.u64 t, %1; cvt.u32.u64 %0, t; }" : "=r"(a) : "l"(p));
    return a;
}
__device__ __forceinline__ unsigned f2tf(float x) {
    unsigned r;
    asm("cvt.rna.tf32.f32 %0, %1;" : "=r"(r) : "f"(x));
    return r;
}
__device__ __forceinline__ void mma_u(float d[4], const unsigned a[4], const unsigned b[2]) {
    asm volatile(
        "mma.sync.aligned.m16n8k8.row.col.f32.tf32.tf32.f32 "
        "{%0,%1,%2,%3}, {%4,%5,%6,%7}, {%8,%9}, {%0,%1,%2,%3};"
        : "+f"(d[0]), "+f"(d[1]), "+f"(d[2]), "+f"(d[3])
        : "r"(a[0]), "r"(a[1]), "r"(a[2]), "r"(a[3]), "r"(b[0]), "r"(b[1]));
}
__device__ __forceinline__ void lds128u(unsigned& a, unsigned& b, unsigned& c, unsigned& d,
                                        unsigned addr) {
    asm volatile("ld.shared.v4.b32 {%0,%1,%2,%3}, [%4];"
                 : "=r"(a), "=r"(b), "=r"(c), "=r"(d) : "r"(addr));
}
__device__ __forceinline__ void lds64u(unsigned& a, unsigned& b, unsigned addr) {
    asm volatile("ld.shared.v2.b32 {%0,%1}, [%2];" : "=r"(a), "=r"(b) : "r"(addr));
}
__device__ __forceinline__ void sts128u(unsigned addr, unsigned a, unsigned b,
                                        unsigned c, unsigned d) {
    asm volatile("st.shared.v4.b32 [%0], {%1,%2,%3,%4};"
                 :: "r"(addr), "r"(a), "r"(b), "r"(c), "r"(d) : "memory");
}
__device__ __forceinline__ void sts64u(unsigned addr, unsigned a, unsigned b) {
    asm volatile("st.shared.v2.b32 [%0], {%1,%2};" :: "r"(addr), "r"(a), "r"(b) : "memory");
}
__device__ __forceinline__ float silu(float x) { return x / (1.f + __expf(-x)); }

// ================================================================
// Node projection kernel (unchanged from R4 — passes, 83us total)
// ================================================================
__device__ __forceinline__ void load_tile_async(float* As, const float* __restrict__ g,
                                                long row0, long rows, int tid) {
    unsigned sbase = smem_u32(As);
#pragma unroll
    for (int i = 0; i < 8; i++) {
        int idx = i * 512 + tid;
        int row = idx >> 5, c16 = idx & 31;
        unsigned dst = sbase + (unsigned)(row * STR + c16 * 4) * 4u;
        long gr = row0 + row;
        const float* src = g + (size_t)(gr < rows ? gr : 0) * 128 + c16 * 4;
        unsigned sz = (gr < rows) ? 16u : 0u;
        asm volatile("cp.async.cg.shared.global [%0], [%1], 16, %2;"
                     :: "r"(dst), "l"(src), "r"(sz));
    }
    asm volatile("cp.async.commit_group;" ::: "memory");
}
__device__ __forceinline__ void stage_w_tf32(unsigned* Ws, const float* __restrict__ w, int tid) {
#pragma unroll
    for (int i = 0; i < 8; i++) {
        int j4 = i * 512 + tid;
        int n  = j4 >> 5, k4 = (j4 & 31) * 4;
        float4 v = *(const float4*)(w + (size_t)n * 128 + k4);
        unsigned* p = Ws + n * STR + k4;
        p[0] = f2tf(v.x); p[1] = f2tf(v.y); p[2] = f2tf(v.z); p[3] = f2tf(v.w);
    }
}
template <bool CVT_A>
__device__ __forceinline__ void warp_gemm32(const float* As, const unsigned* Bs,
                                            int mbase, int nbase, int lane,
                                            float acc[2][4][4]) {
    int r = lane >> 2, c = lane & 3;
    const float*    ap = As + (mbase + r) * STR + c;
    const unsigned* bp = Bs + (nbase + r) * STR + c;
#pragma unroll
    for (int kk = 0; kk < 128; kk += 8) {
        unsigned a[2][4], b[4][2];
#pragma unroll
        for (int mi = 0; mi < 2; mi++) {
            const float* p = ap + mi * (16 * STR) + kk;
            float x0 = p[0], x1 = p[8 * STR], x2 = p[4], x3 = p[8 * STR + 4];
            if (CVT_A) {
                a[mi][0] = f2tf(x0); a[mi][1] = f2tf(x1);
                a[mi][2] = f2tf(x2); a[mi][3] = f2tf(x3);
            } else {
                a[mi][0] = __float_as_uint(x0); a[mi][1] = __float_as_uint(x1);
                a[mi][2] = __float_as_uint(x2); a[mi][3] = __float_as_uint(x3);
            }
        }
#pragma unroll
        for (int ni = 0; ni < 4; ni++) {
            const unsigned* pb = bp + ni * (8 * STR) + kk;
            b[ni][0] = pb[0]; b[ni][1] = pb[4];
        }
#pragma unroll
        for (int mi = 0; mi < 2; mi++)
#pragma unroll
            for (int ni = 0; ni < 4; ni++)
                mma_u(acc[mi][ni], a[mi], b[ni]);
    }
}
__device__ __forceinline__ void store_C32(float* Cs, float acc[2][4][4],
                                          int mbase, int nbase, int lane) {
    int r = lane >> 2, c2 = (lane & 3) * 2;
#pragma unroll
    for (int mi = 0; mi < 2; mi++)
#pragma unroll
        for (int ni = 0; ni < 4; ni++) {
            int row = mbase + mi * 16 + r, col = nbase + ni * 8 + c2;
            *(float2*)(Cs + row * CSTR + col)       = make_float2(acc[mi][ni][0], acc[mi][ni][1]);
            *(float2*)(Cs + (row + 8) * CSTR + col) = make_float2(acc[mi][ni][2], acc[mi][ni][3]);
        }
}

__global__ void __launch_bounds__(512, 1)
node_proj2(const float* __restrict__ feat, const float* __restrict__ w,
           const float* __restrict__ bias, int which, int nrows, int ntiles) {
    extern __shared__ float smf[];
    float*    As = smf;
    unsigned* Ws = (unsigned*)(smf + TWORDS);
    float*    Cs = smf + 2 * TWORDS;
    __shared__ float sbias[128];

    int tid = threadIdx.x, lane = tid & 31, wid = tid >> 5;
    int mbase = (wid >> 2) * 32, nbase = (wid & 3) * 32;
    int e = tid >> 2, q = tid & 3;

    stage_w_tf32(Ws, w, tid);
    if (tid < 128) sbias[tid] = bias ? bias[tid] : 0.f;

    long t = blockIdx.x;
    if (t < ntiles) load_tile_async(As, feat, t * 128, nrows, tid);
    __syncthreads();

    float* outp = which ? g_mdst : g_msrc;

    for (; t < ntiles; t += gridDim.x) {
        asm volatile("cp.async.wait_group 0;" ::: "memory");
        __syncthreads();

        float acc[2][4][4];
#pragma unroll
        for (int mi = 0; mi < 2; mi++)
#pragma unroll
            for (int ni = 0; ni < 4; ni++)
#pragma unroll
                for (int k = 0; k < 4; k++) acc[mi][ni][k] = 0.f;
        warp_gemm32<true>(As, Ws, mbase, nbase, lane, acc);
        __syncthreads();

        long nt = t + gridDim.x;
        if (nt < ntiles) load_tile_async(As, feat, nt * 128, nrows, tid);

        store_C32(Cs, acc, mbase, nbase, lane);
        __syncthreads();

        long gr = t * 128 + e;
        if (gr < nrows) {
            float* po = outp + (size_t)gr * 128;
            const float* rp = Cs + e * CSTR;
#pragma unroll
            for (int i = 0; i < 8; i++) {
                int k = q * 4 + i * 16;
                float4 v = *(const float4*)(rp + k);
                v.x += sbias[k + 0]; v.y += sbias[k + 1];
                v.z += sbias[k + 2]; v.w += sbias[k + 3];
                *(float4*)(po + k) = v;
            }
        }
    }
}

// ================================================================
// Edge kernel: fragment-packed tf32 pipeline
//
// dynamic smem layout (bytes):
//   [0, 67584)          buf : packed-A (64KB) / C1 row-major (132-stride) / packed-X
//   [67584, 133120)     PB1 : packed W1 (tf32 pairs)
//   [133120, 198656)    PB2 : packed W2
//
// packed A/X cell (16B) at byte  g*8192 + k8*512 + (c*8+r)*16 :
//   { M[g16+r][k8*8+c], M[g16+r+8][k8*8+c], M[g16+r][k8*8+c+4], M[g16+r+8][k8*8+c+4] }
// packed W pair (8B) at byte  ng*4096 + k8*256 + c*64 + r*8 :
//   { W[ng*8+r][k8*8+c], W[ng*8+r][k8*8+c+4] }
// ================================================================
#define BUF_BYTES   67584u
#define PB1_OFF     67584u
#define PB2_OFF     133120u
#define EDGE_SMEM   198656

__device__ __forceinline__ void gemm_packed(unsigned Ab, unsigned Bb, int wm, int wn,
                                            int lane, float acc[2][4][4]) {
    unsigned cell = (unsigned)((lane & 3) * 8 + (lane >> 2));
    unsigned a0 = Ab + (unsigned)(wm * 2) * 8192u + cell * 16u;
    unsigned a1 = a0 + 8192u;
    unsigned b0 = Bb + (unsigned)(wn * 4) * 4096u + cell * 8u;
#pragma unroll
    for (int k8 = 0; k8 < 16; k8++) {
        unsigned a[2][4], b[4][2];
        lds128u(a[0][0], a[0][1], a[0][2], a[0][3], a0 + (unsigned)k8 * 512u);
        lds128u(a[1][0], a[1][1], a[1][2], a[1][3], a1 + (unsigned)k8 * 512u);
#pragma unroll
        for (int ni = 0; ni < 4; ni++)
            lds64u(b[ni][0], b[ni][1], b0 + (unsigned)ni * 4096u + (unsigned)k8 * 256u);
#pragma unroll
        for (int mi = 0; mi < 2; mi++)
#pragma unroll
            for (int ni = 0; ni < 4; ni++)
                mma_u(acc[mi][ni], a[mi], b[ni]);
    }
}

__device__ __forceinline__ void stage_wB_packed(unsigned PB, const float* __restrict__ w,
                                                int tid) {
#pragma unroll
    for (int i = 0; i < 4; i++) {
        int ch = tid + i * 512;                 // 2048 (n, k8) chunks
        int n = ch >> 4, k8 = ch & 15;
        float4 lo = *(const float4*)(w + (size_t)n * 128 + k8 * 8);
        float4 hi = *(const float4*)(w + (size_t)n * 128 + k8 * 8 + 4);
        unsigned wl[4] = {f2tf(lo.x), f2tf(lo.y), f2tf(lo.z), f2tf(lo.w)};
        unsigned wh[4] = {f2tf(hi.x), f2tf(hi.y), f2tf(hi.z), f2tf(hi.w)};
        unsigned base = PB + (unsigned)(n >> 3) * 4096u + (unsigned)k8 * 256u
                      + (unsigned)(n & 7) * 8u;
#pragma unroll
        for (int c = 0; c < 4; c++) sts64u(base + (unsigned)c * 64u, wl[c], wh[c]);
    }
}

// thread -> 2 chunks; chunk ch = tid + i*512 : g=ch>>7, r=(ch>>4)&7, k8=ch&15
__device__ __forceinline__ void prefetchA(float4 av[2][4], const float* __restrict__ efeat,
                                          long t, int E, int tid) {
    const float4 z = make_float4(0.f, 0.f, 0.f, 0.f);
#pragma unroll
    for (int i = 0; i < 2; i++) {
        int ch = tid + i * 512;
        int g = ch >> 7, r = (ch >> 4) & 7, k8 = ch & 15;
        long elo = t * 128 + g * 16 + r, ehi = elo + 8;
        const float* p0 = efeat + (size_t)(elo < E ? elo : 0) * 128 + k8 * 8;
        const float* p1 = efeat + (size_t)(ehi < E ? ehi : 0) * 128 + k8 * 8;
        av[i][0] = (elo < E) ? __ldg((const float4*)p0)       : z;
        av[i][1] = (elo < E) ? __ldg((const float4*)(p0 + 4)) : z;
        av[i][2] = (ehi < E) ? __ldg((const float4*)p1)       : z;
        av[i][3] = (ehi < E) ? __ldg((const float4*)(p1 + 4)) : z;
    }
}

__device__ __forceinline__ void stageA(unsigned Ab, const float4 av[2][4], int tid) {
#pragma unroll
    for (int i = 0; i < 2; i++) {
        int ch = tid + i * 512;
        int g = ch >> 7, r = (ch >> 4) & 7, k8 = ch & 15;
        unsigned lo[8], hi[8];
        lo[0] = f2tf(av[i][0].x); lo[1] = f2tf(av[i][0].y);
        lo[2] = f2tf(av[i][0].z); lo[3] = f2tf(av[i][0].w);
        lo[4] = f2tf(av[i][1].x); lo[5] = f2tf(av[i][1].y);
        lo[6] = f2tf(av[i][1].z); lo[7] = f2tf(av[i][1].w);
        hi[0] = f2tf(av[i][2].x); hi[1] = f2tf(av[i][2].y);
        hi[2] = f2tf(av[i][2].z); hi[3] = f2tf(av[i][2].w);
        hi[4] = f2tf(av[i][3].x); hi[5] = f2tf(av[i][3].y);
        hi[6] = f2tf(av[i][3].z); hi[7] = f2tf(av[i][3].w);
        unsigned base = Ab + (unsigned)g * 8192u + (unsigned)k8 * 512u + (unsigned)r * 16u;
#pragma unroll
        for (int c = 0; c < 4; c++)
            sts128u(base + (unsigned)c * 128u, lo[c], hi[c], lo[c + 4], hi[c + 4]);
    }
}

__device__ __forceinline__ void prefetchG(float4 gs[2][4], float4 gd[2][4],
                                          const int* __restrict__ si,
                                          const int* __restrict__ di,
                                          long t, int E, int tid) {
#pragma unroll
    for (int i = 0; i < 2; i++) {
        int ch = tid + i * 512;
        int g = ch >> 7, r = (ch >> 4) & 7, k8 = ch & 15;
        long elo = t * 128 + g * 16 + r, ehi = elo + 8;
        int slo = (elo < E) ? __ldg(si + elo) : 0;
        int shi = (ehi < E) ? __ldg(si + ehi) : 0;
        int dlo = (elo < E) ? __ldg(di + elo) : 0;
        int dhi = (ehi < E) ? __ldg(di + ehi) : 0;
        const float* p;
        p = g_msrc + (size_t)slo * 128 + k8 * 8;
        gs[i][0] = __ldg((const float4*)p); gs[i][1] = __ldg((const float4*)(p + 4));
        p = g_msrc + (size_t)shi * 128 + k8 * 8;
        gs[i][2] = __ldg((const float4*)p); gs[i][3] = __ldg((const float4*)(p + 4));
        p = g_mdst + (size_t)dlo * 128 + k8 * 8;
        gd[i][0] = __ldg((const float4*)p); gd[i][1] = __ldg((const float4*)(p + 4));
        p = g_mdst + (size_t)dhi * 128 + k8 * 8;
        gd[i][2] = __ldg((const float4*)p); gd[i][3] = __ldg((const float4*)(p + 4));
    }
}

__global__ void __launch_bounds__(512, 1)
edge_mma3(const float* __restrict__ efeat,
          const int* __restrict__ src_idx, const int* __restrict__ dst_idx,
          const float* __restrict__ w1, const float* __restrict__ w2,
          const float* __restrict__ b2f, const float* __restrict__ gammaf,
          const float* __restrict__ betaf, float* __restrict__ out,
          int E, int ntiles) {
    extern __shared__ float smf[];
    __shared__ float sb2[128], sgm[128], sbt[128];
    __shared__ float red1[4][128], red2[4][128];

    int tid = threadIdx.x, lane = tid & 31, wid = tid >> 5;
    int r = lane >> 2, cc = lane & 3;
    int wm = wid >> 2, wn = wid & 3;
    int mbase = wm * 32, nbase = wn * 32;

    unsigned sbase = smem_u32(smf);
    unsigned Ab = sbase;                 // packed A / X
    unsigned PB1 = sbase + PB1_OFF;
    unsigned PB2 = sbase + PB2_OFF;

    stage_wB_packed(PB1, w1, tid);
    stage_wB_packed(PB2, w2, tid);
    if (tid < 128) { sb2[tid] = b2f[tid]; sgm[tid] = gammaf[tid]; sbt[tid] = betaf[tid]; }

    long t = blockIdx.x;
    float4 av[2][4], gs[2][4], gd[2][4];
    if (t < ntiles) {
        prefetchA(av, efeat, t, E, tid);
        prefetchG(gs, gd, src_idx, dst_idx, t, E, tid);
    }
    __syncthreads();                      // PB ready

    for (; t < ntiles; t += gridDim.x) {
        // P0: stage packed A (cvt + STS)
        stageA(Ab, av, tid);
        __syncthreads();

        // P1: GEMM1
        float acc[2][4][4];
#pragma unroll
        for (int mi = 0; mi < 2; mi++)
#pragma unroll
            for (int ni = 0; ni < 4; ni++)
#pragma unroll
                for (int k = 0; k < 4; k++) acc[mi][ni][k] = 0.f;
        gemm_packed(Ab, PB1, wm, wn, lane, acc);
        __syncthreads();

        // P2: C1 -> buf row-major (over dead packed-A)
        store_C32(smf, acc, mbase, nbase, lane);
        __syncthreads();

        // P3: epilogue1 in regs: C1 + gathers -> SiLU -> tf32
        unsigned xlo[2][8], xhi[2][8];
#pragma unroll
        for (int i = 0; i < 2; i++) {
            int ch = tid + i * 512;
            int g = ch >> 7, rr = (ch >> 4) & 7, k8 = ch & 15;
            int rowlo = g * 16 + rr, rowhi = rowlo + 8;
            const float4* plo = (const float4*)(smf + rowlo * CSTR + k8 * 8);
            const float4* phi = (const float4*)(smf + rowhi * CSTR + k8 * 8);
            float4 l0 = plo[0], l1 = plo[1], h0 = phi[0], h1 = phi[1];
            float lv[8] = {l0.x, l0.y, l0.z, l0.w, l1.x, l1.y, l1.z, l1.w};
            float hv[8] = {h0.x, h0.y, h0.z, h0.w, h1.x, h1.y, h1.z, h1.w};
            const float* s0 = (const float*)&gs[i][0];
            const float* s1 = (const float*)&gs[i][2];
            const float* d0 = (const float*)&gd[i][0];
            const float* d1 = (const float*)&gd[i][2];
#pragma unroll
            for (int j = 0; j < 8; j++) {
                xlo[i][j] = f2tf(silu(lv[j] + s0[j] + d0[j]));
                xhi[i][j] = f2tf(silu(hv[j] + s1[j] + d1[j]));
            }
        }
        __syncthreads();                  // all C1 reads done before X writes

        // P4: STS packed X; start A prefetch for next tile
        long nt = t + gridDim.x;
#pragma unroll
        for (int i = 0; i < 2; i++) {
            int ch = tid + i * 512;
            int g = ch >> 7, rr = (ch >> 4) & 7, k8 = ch & 15;
            unsigned base = Ab + (unsigned)g * 8192u + (unsigned)k8 * 512u + (unsigned)rr * 16u;
#pragma unroll
            for (int c = 0; c < 4; c++)
                sts128u(base + (unsigned)c * 128u,
                        xlo[i][c], xhi[i][c], xlo[i][c + 4], xhi[i][c + 4]);
        }
        if (nt < ntiles) prefetchA(av, efeat, nt, E, tid);
        __syncthreads();

        // P5: GEMM2
        float acc2[2][4][4];
#pragma unroll
        for (int mi = 0; mi < 2; mi++)
#pragma unroll
            for (int ni = 0; ni < 4; ni++)
#pragma unroll
                for (int k = 0; k < 4; k++) acc2[mi][ni][k] = 0.f;
        gemm_packed(Ab, PB2, wm, wn, lane, acc2);
        __syncthreads();

        // P6: gather prefetch for next tile; LN partial sums
        if (nt < ntiles) prefetchG(gs, gd, src_idx, dst_idx, nt, E, tid);

        float s1[2][2], s2[2][2];
#pragma unroll
        for (int mi = 0; mi < 2; mi++)
#pragma unroll
            for (int h = 0; h < 2; h++) { s1[mi][h] = 0.f; s2[mi][h] = 0.f; }
#pragma unroll
        for (int mi = 0; mi < 2; mi++)
#pragma unroll
            for (int ni = 0; ni < 4; ni++) {
                int col0 = nbase + ni * 8 + cc * 2;
                float b0 = sb2[col0], b1 = sb2[col0 + 1];
                float y0 = acc2[mi][ni][0] + b0, y1 = acc2[mi][ni][1] + b1;
                float y2 = acc2[mi][ni][2] + b0, y3 = acc2[mi][ni][3] + b1;
                s1[mi][0] += y0 + y1; s2[mi][0] += y0 * y0 + y1 * y1;
                s1[mi][1] += y2 + y3; s2[mi][1] += y2 * y2 + y3 * y3;
            }
#pragma unroll
        for (int mi = 0; mi < 2; mi++)
#pragma unroll
            for (int h = 0; h < 2; h++) {
                s1[mi][h] += __shfl_xor_sync(0xffffffffu, s1[mi][h], 1);
                s1[mi][h] += __shfl_xor_sync(0xffffffffu, s1[mi][h], 2);
                s2[mi][h] += __shfl_xor_sync(0xffffffffu, s2[mi][h], 1);
                s2[mi][h] += __shfl_xor_sync(0xffffffffu, s2[mi][h], 2);
            }
        if (cc == 0) {
#pragma unroll
            for (int mi = 0; mi < 2; mi++)
#pragma unroll
                for (int h = 0; h < 2; h++) {
                    int row = mbase + mi * 16 + h * 8 + r;
                    red1[wn][row] = s1[mi][h];
                    red2[wn][row] = s2[mi][h];
                }
        }
        __syncthreads();

        // P7: LN finalize + store
        long e0 = t * 128;
#pragma unroll
        for (int mi = 0; mi < 2; mi++)
#pragma unroll
            for (int h = 0; h < 2; h++) {
                int row = mbase + mi * 16 + h * 8 + r;
                float S1 = red1[0][row] + red1[1][row] + red1[2][row] + red1[3][row];
                float S2 = red2[0][row] + red2[1][row] + red2[2][row] + red2[3][row];
                float mean = S1 * (1.f / 128.f);
                float var  = S2 * (1.f / 128.f) - mean * mean;
                float inv  = rsqrtf(var + 1e-5f);
                long ge = e0 + row;
                if (ge < E) {
                    float* po = out + (size_t)ge * 128;
#pragma unroll
                    for (int ni = 0; ni < 4; ni++) {
                        int col0 = nbase + ni * 8 + cc * 2;
                        float ya = acc2[mi][ni][2 * h + 0] + sb2[col0];
                        float yb = acc2[mi][ni][2 * h + 1] + sb2[col0 + 1];
                        float oa = (ya - mean) * inv * sgm[col0]     + sbt[col0];
                        float ob = (yb - mean) * inv * sgm[col0 + 1] + sbt[col0 + 1];
                        *(float2*)(po + col0) = make_float2(oa, ob);
                    }
                }
            }
        __syncthreads();
    }
}

// ---------------- launcher ----------------
extern "C" void kernel_launch(void* const* d_in, const int* in_sizes, int n_in,
                              void* d_out, int out_size) {
    const float* efeat    = (const float*)d_in[0];
    const float* src_feat = (const float*)d_in[1];
    const float* dst_feat = (const float*)d_in[2];
    const int*   src_idx  = (const int*)d_in[3];
    const int*   dst_idx  = (const int*)d_in[4];
    const float* w_ef     = (const float*)d_in[5];
    const float* w_src    = (const float*)d_in[6];
    const float* w_dst    = (const float*)d_in[7];
    const float* b1       = (const float*)d_in[8];
    const float* w2       = (const float*)d_in[9];
    const float* b2       = (const float*)d_in[10];
    const float* gamma    = (const float*)d_in[11];
    const float* beta     = (const float*)d_in[12];

    int E  = in_sizes[3];
    int Nn = in_sizes[1] / 128;

    const int node_smem = 3 * TWORDS * (int)sizeof(float);
    cudaFuncSetAttribute(node_proj2,
                         cudaFuncAttributeMaxDynamicSharedMemorySize, node_smem);
    cudaFuncSetAttribute(edge_mma3,
                         cudaFuncAttributeMaxDynamicSharedMemorySize, EDGE_SMEM);

    int nsm = 148;
    cudaDeviceGetAttribute(&nsm, cudaDevAttrMultiProcessorCount, 0);

    int ntilesN = (Nn + 127) / 128;
    int gridN = ntilesN < nsm ? ntilesN : nsm;
    node_proj2<<<gridN, 512, node_smem>>>(src_feat, w_src, nullptr, 0, Nn, ntilesN);
    node_proj2<<<gridN, 512, node_smem>>>(dst_feat, w_dst, b1,      1, Nn, ntilesN);

    int ntiles = (E + 127) / 128;
    int gridE = ntiles < nsm ? ntiles : nsm;
    edge_mma3<<<gridE, 512, EDGE_SMEM>>>(efeat, src_idx, dst_idx, w_ef, w2,
                                         b2, gamma, beta, (float*)d_out, E, ntiles);
}